// round 4
// baseline (speedup 1.0000x reference)
#include <cuda_runtime.h>
#include <cstdint>

// Problem constants (fixed by the reference)
#define CIN   64
#define COUT  64
#define KOFF  27
#define MPAIR 131072
#define NOUT  262144
#define NIN   262144
#define EPS   1e-5f
#define SLOPE 0.01f

// smem layout for conv kernel (dynamic):
//   [0, 16896)  : WsP — lane-permuted tf32 W tile, 32 lanes x 132 uints
//   [16896, ..) : buf0, buf1 — 2 x (128 staging rows x 68 floats)
#define WSP_STRIDE 132                   // uints per lane (128 + 4 pad)
#define WSP_BYTES  (32 * WSP_STRIDE * 4) // 16896
#define BUF_STRIDE 68                    // floats; 272B row stride, 16B mult
#define BUF_BYTES  (128 * BUF_STRIDE * 4)
#define SMEM_BYTES (WSP_BYTES + 2 * BUF_BYTES)

// Pre-converted tf32 operands (device scratch; no runtime allocation)
__device__ uint32_t g_featsT[NIN * CIN];      // 64 MB, lane-permuted rows
__device__ uint32_t g_WT[KOFF * CIN * COUT];  // 432 KB

// BN statistics scratch
__device__ float g_sum[COUT];
__device__ float g_sumsq[COUT];

__device__ __forceinline__ uint32_t smem_u32(const void* p) {
    uint32_t a;
    asm("{ .reg .u64 t; cvta.to.shared.u64 t, %1; cvt.u32.u64 %0, t; }"
        : "=r"(a) : "l"(p));
    return a;
}
__device__ __forceinline__ uint32_t to_tf32(float f) {
    uint32_t t;
    asm("cvt.rna.tf32.f32 %0, %1;" : "=r"(t) : "f"(f));
    return t;
}

// ---------------------------------------------------------------------------
// Kernel 0: zero output accumulator + stats scratch
// ---------------------------------------------------------------------------
__global__ void zero_kernel(float4* __restrict__ out4) {
    int idx = blockIdx.x * blockDim.x + threadIdx.x;   // 4,194,304 float4s
    out4[idx] = make_float4(0.f, 0.f, 0.f, 0.f);
    if (blockIdx.x == 0 && threadIdx.x < COUT) {
        g_sum[threadIdx.x]   = 0.f;
        g_sumsq[threadIdx.x] = 0.f;
    }
}

// ---------------------------------------------------------------------------
// Kernel 0b: pre-convert feats (permuted) and W to tf32 bits.
// feats row permutation: element c -> position (c&3)*16 + (c>>2), so that
// lane (r,a) of the mma consumes 16 contiguous uints at offset a*16.
// grid = 16384 x 256 (4 elements per thread); blocks 0..26 also convert W.
// ---------------------------------------------------------------------------
__global__ void __launch_bounds__(256)
precvt_kernel(const float* __restrict__ feats, const float* __restrict__ W)
{
    const int tid = threadIdx.x;
    const int t4  = blockIdx.x * 256 + tid;        // 0 .. 4,194,303
    const int row = t4 >> 4;
    const int p   = (t4 & 15) << 2;                // position, multiple of 4
    const int a_  = p >> 4;
    const int q   = p & 15;
    const int c   = (q << 2) + a_;                 // source element index

    const float* src = feats + (size_t)row * CIN;
    uint4 v;
    v.x = to_tf32(src[c]);
    v.y = to_tf32(src[c + 4]);
    v.z = to_tf32(src[c + 8]);
    v.w = to_tf32(src[c + 12]);
    *reinterpret_cast<uint4*>(g_featsT + (size_t)row * CIN + p) = v;

    if (blockIdx.x < KOFF) {
        const float* Wk = W + blockIdx.x * (CIN * COUT);
        uint32_t* dst = g_WT + blockIdx.x * (CIN * COUT);
        for (int i = tid; i < CIN * COUT; i += 256)
            dst[i] = to_tf32(Wk[i]);
    }
}

// ---------------------------------------------------------------------------
// Kernel 1: sparse conv. vector gather (preconverted tf32) -> mma.sync ->
//           smem stage -> cp.reduce.async.bulk scatter (double buffered).
// Block: 256 threads (8 warps). Warp: 16 pairs/tile, block 128, 4 tiles.
// grid = (M/512, K)
// ---------------------------------------------------------------------------
__global__ void __launch_bounds__(256)
conv_kernel(const int* __restrict__ in_map,
            const int* __restrict__ out_map,
            float*     __restrict__ out)
{
    extern __shared__ char dynsmem[];
    uint32_t* WsP  = reinterpret_cast<uint32_t*>(dynsmem);
    float*    buf0 = reinterpret_cast<float*>(dynsmem + WSP_BYTES);
    float*    buf1 = buf0 + 128 * BUF_STRIDE;

    const int k   = blockIdx.y;
    const int tid = threadIdx.x;

    // Build lane-exclusive permuted W tile:
    // element (ci, co) belongs to lane (co%8)*4 + (ci%4),
    // at index kk*16 + j*2 + pair, kk=ci/8, j=co/8, pair=(ci>>2)&1.
    {
        const uint32_t* WTk = g_WT + k * (CIN * COUT);
        for (int i = tid; i < CIN * COUT; i += 256) {
            int ci = i >> 6, co = i & 63;
            int lanep = ((co & 7) << 2) + (ci & 3);
            int idx = ((ci >> 3) << 4) + ((co >> 3) << 1) + ((ci >> 2) & 1);
            WsP[lanep * WSP_STRIDE + idx] = WTk[i];
        }
    }
    __syncthreads();

    const int warp = tid >> 5;
    const int lane = tid & 31;
    const int r = lane >> 2;   // 0..7
    const int a = lane & 3;    // 0..3

    const int* im = in_map  + k * MPAIR;
    const int* om = out_map + k * MPAIR;
    const uint32_t* Bl = WsP + lane * WSP_STRIDE;

    #pragma unroll 1
    for (int t = 0; t < 4; t++) {
        const int base = (blockIdx.x * 4 + t) * 128 + warp * 16;
        const int p0 = base + r;
        const int p1 = p0 + 8;

        // Gather two permuted tf32 rows: 16 contiguous uints each at a*16.
        const uint4* r0p = reinterpret_cast<const uint4*>(
            g_featsT + (size_t)im[p0] * CIN + (a << 4));
        const uint4* r1p = reinterpret_cast<const uint4*>(
            g_featsT + (size_t)im[p1] * CIN + (a << 4));
        uint32_t A0[16], A1[16];
        #pragma unroll
        for (int i = 0; i < 4; i++) {
            *reinterpret_cast<uint4*>(A0 + 4 * i) = r0p[i];
            *reinterpret_cast<uint4*>(A1 + 4 * i) = r1p[i];
        }

        float acc[8][4];
        #pragma unroll
        for (int j = 0; j < 8; j++)
            #pragma unroll
            for (int q = 0; q < 4; q++) acc[j][q] = 0.f;

        #pragma unroll
        for (int kk = 0; kk < 8; kk++) {
            uint32_t Bk[16];
            #pragma unroll
            for (int i = 0; i < 4; i++)
                *reinterpret_cast<uint4*>(Bk + 4 * i) =
                    *reinterpret_cast<const uint4*>(Bl + kk * 16 + 4 * i);

            const uint32_t a0 = A0[2 * kk],     a1 = A1[2 * kk];
            const uint32_t a2 = A0[2 * kk + 1], a3 = A1[2 * kk + 1];

            #pragma unroll
            for (int j = 0; j < 8; j++) {
                asm volatile(
                    "mma.sync.aligned.m16n8k8.row.col.f32.tf32.tf32.f32 "
                    "{%0,%1,%2,%3}, {%4,%5,%6,%7}, {%8,%9}, {%0,%1,%2,%3};"
                    : "+f"(acc[j][0]), "+f"(acc[j][1]),
                      "+f"(acc[j][2]), "+f"(acc[j][3])
                    : "r"(a0), "r"(a1), "r"(a2), "r"(a3),
                      "r"(Bk[2 * j]), "r"(Bk[2 * j + 1]));
            }
        }

        // --- Epilogue: stage 16 rows, scatter via TMA bulk reduce-add. ---
        float* wbuf = ((t & 1) ? buf1 : buf0) + warp * 16 * BUF_STRIDE;

        // Double buffer: ensure the group that used THIS buffer (2 tiles
        // ago) has finished reading its smem staging rows.
        asm volatile("cp.async.bulk.wait_group.read 1;" ::: "memory");
        __syncwarp();

        // mma D layout: lane(r,a) holds D[r, j*8+2a..+1], D[r+8, ...].
        #pragma unroll
        for (int j = 0; j < 8; j++) {
            *reinterpret_cast<float2*>(wbuf + r * BUF_STRIDE + j * 8 + 2 * a)
                = make_float2(acc[j][0], acc[j][1]);
            *reinterpret_cast<float2*>(wbuf + (r + 8) * BUF_STRIDE + j * 8 + 2 * a)
                = make_float2(acc[j][2], acc[j][3]);
        }
        __syncwarp();
        asm volatile("fence.proxy.async.shared::cta;" ::: "memory");

        if (lane < 16) {
            float* dst = out + (size_t)om[base + lane] * COUT;
            uint32_t src = smem_u32(wbuf + lane * BUF_STRIDE);
            asm volatile(
                "cp.reduce.async.bulk.global.shared::cta.bulk_group.add.f32 "
                "[%0], [%1], %2;"
                :: "l"(dst), "r"(src), "r"(256) : "memory");
        }
        asm volatile("cp.async.bulk.commit_group;" ::: "memory");
    }

    // All reduce writes must complete before kernel end.
    asm volatile("cp.async.bulk.wait_group 0;" ::: "memory");
}

// ---------------------------------------------------------------------------
// Kernel 2: per-column sum / sumsq over the conv output
// ---------------------------------------------------------------------------
__global__ void stats_kernel(const float* __restrict__ out) {
    __shared__ float ssum[256], ssq[256];
    const int tid = threadIdx.x;
    const int col = tid & 63;
    const int q   = tid >> 6;
    const int rowbase = blockIdx.x * 1024;

    float s = 0.f, s2 = 0.f;
    #pragma unroll 4
    for (int i = 0; i < 256; i++) {
        float v = out[(size_t)(rowbase + i * 4 + q) * COUT + col];
        s += v; s2 += v * v;
    }
    ssum[tid] = s; ssq[tid] = s2;
    __syncthreads();
    if (q == 0) {
        s  = ssum[col] + ssum[col + 64] + ssum[col + 128] + ssum[col + 192];
        s2 = ssq[col]  + ssq[col + 64]  + ssq[col + 128]  + ssq[col + 192];
        atomicAdd(&g_sum[col], s);
        atomicAdd(&g_sumsq[col], s2);
    }
}

// ---------------------------------------------------------------------------
// Kernel 3: BN affine + LeakyReLU, in place, float4 vectorized
// ---------------------------------------------------------------------------
__global__ void apply_kernel(float* __restrict__ out,
                             const float* __restrict__ gamma,
                             const float* __restrict__ beta)
{
    __shared__ float sc[COUT], bi[COUT];
    const int tid = threadIdx.x;
    if (tid < COUT) {
        const float inv_n = 1.f / (float)NOUT;
        float mean = g_sum[tid] * inv_n;
        float var  = g_sumsq[tid] * inv_n - mean * mean;
        float s = gamma[tid] * rsqrtf(var + EPS);
        sc[tid] = s;
        bi[tid] = beta[tid] - mean * s;
    }
    __syncthreads();

    const int idx = blockIdx.x * blockDim.x + tid;   // over 4,194,304 float4
    float4* o4 = reinterpret_cast<float4*>(out);
    float4 v = o4[idx];
    const int c = (idx & 15) * 4;
    float y0 = v.x * sc[c + 0] + bi[c + 0];
    float y1 = v.y * sc[c + 1] + bi[c + 1];
    float y2 = v.z * sc[c + 2] + bi[c + 2];
    float y3 = v.w * sc[c + 3] + bi[c + 3];
    v.x = (y0 >= 0.f) ? y0 : SLOPE * y0;
    v.y = (y1 >= 0.f) ? y1 : SLOPE * y1;
    v.z = (y2 >= 0.f) ? y2 : SLOPE * y2;
    v.w = (y3 >= 0.f) ? y3 : SLOPE * y3;
    o4[idx] = v;
}

// ---------------------------------------------------------------------------
// Launch
// inputs (metadata order): feats f32[N_IN*64], W f32[27*64*64], gamma f32[64],
//   beta f32[64], in_map i32[27*M], out_map i32[27*M], num_out i32[1]
// ---------------------------------------------------------------------------
extern "C" void kernel_launch(void* const* d_in, const int* in_sizes, int n_in,
                              void* d_out, int out_size)
{
    const float* feats   = (const float*)d_in[0];
    const float* W       = (const float*)d_in[1];
    const float* gamma   = (const float*)d_in[2];
    const float* beta    = (const float*)d_in[3];
    const int*   in_map  = (const int*)d_in[4];
    const int*   out_map = (const int*)d_in[5];
    float*       out     = (float*)d_out;

    const int n_f4 = (NOUT * COUT) / 4;          // 4,194,304

    zero_kernel<<<n_f4 / 256, 256>>>(reinterpret_cast<float4*>(out));
    precvt_kernel<<<16384, 256>>>(feats, W);

    cudaFuncSetAttribute(conv_kernel,
                         cudaFuncAttributeMaxDynamicSharedMemorySize,
                         SMEM_BYTES);
    dim3 grid(MPAIR / 512, KOFF);                // 256 x 27
    conv_kernel<<<grid, 256, SMEM_BYTES>>>(in_map, out_map, out);

    stats_kernel<<<256, 256>>>(out);

    apply_kernel<<<n_f4 / 256, 256>>>(out, gamma, beta);
}

// round 5
// speedup vs baseline: 1.4746x; 1.4746x over previous
#include <cuda_runtime.h>
#include <cuda_fp16.h>
#include <cstdint>

// Problem constants (fixed by the reference)
#define CIN   64
#define COUT  64
#define KOFF  27
#define MPAIR 131072
#define NOUT  262144
#define NIN   262144
#define EPS   1e-5f
#define SLOPE 0.01f

// smem layout for conv kernel (dynamic):
//   [0, 8704)   : WsP — per-lane fp16x2 W blocks, 32 lanes x 68 uints
//   [8704, ..)  : buf0, buf1 — 2 x (128 staging rows x 68 floats)
#define WSP_STRIDE 68                    // uints per lane (64 + 4 pad)
#define WSP_BYTES  (32 * WSP_STRIDE * 4) // 8704
#define BUF_STRIDE 68                    // floats; 272B row stride, 16B mult
#define BUF_BYTES  (128 * BUF_STRIDE * 4)
#define SMEM_BYTES (WSP_BYTES + 2 * BUF_BYTES)

// Pre-converted fp16 operands (device scratch; no runtime allocation)
// feats row layout (32 uints = 64 fp16): uint index p = a*8 + kk*2 + h
// holds half2( feats[ci], feats[ci+1] ), ci = kk*16 + 2a + 8h.
__device__ uint32_t g_featsH[NIN * 32];          // 33.5 MB
// W layout per k: 32 lanes x 64 uints; lane (r,a), uint kk*16 + j*2 + h
// holds half2( W[ci][co], W[ci+1][co] ), ci = kk*16+2a+8h, co = j*8+r.
__device__ uint32_t g_WH[KOFF * 2048];           // 216 KB

// BN statistics scratch
__device__ float g_sum[COUT];
__device__ float g_sumsq[COUT];

__device__ __forceinline__ uint32_t smem_u32(const void* p) {
    uint32_t a;
    asm("{ .reg .u64 t; cvta.to.shared.u64 t, %1; cvt.u32.u64 %0, t; }"
        : "=r"(a) : "l"(p));
    return a;
}

// ---------------------------------------------------------------------------
// Kernel 0: zero output accumulator + stats scratch
// ---------------------------------------------------------------------------
__global__ void zero_kernel(float4* __restrict__ out4) {
    int idx = blockIdx.x * blockDim.x + threadIdx.x;   // 4,194,304 float4s
    out4[idx] = make_float4(0.f, 0.f, 0.f, 0.f);
    if (blockIdx.x == 0 && threadIdx.x < COUT) {
        g_sum[threadIdx.x]   = 0.f;
        g_sumsq[threadIdx.x] = 0.f;
    }
}

// ---------------------------------------------------------------------------
// Kernel 0b: pre-convert feats and W to fp16 in mma-fragment layouts.
// grid = 8192 x 256: each thread produces 4 uints of g_featsH.
// Blocks 0..26 additionally pack W[k].
// ---------------------------------------------------------------------------
__global__ void __launch_bounds__(256)
precvt_kernel(const float* __restrict__ feats, const float* __restrict__ W)
{
    const int tid = threadIdx.x;
    const int t4  = blockIdx.x * 256 + tid;        // 0 .. 2,097,151
    const int row = t4 >> 3;
    const int p0  = (t4 & 7) << 2;                 // first of 4 uint slots

    const float* src = feats + (size_t)row * CIN;
    uint32_t v[4];
    #pragma unroll
    for (int i = 0; i < 4; i++) {
        const int up = p0 + i;
        const int a  = up >> 3;
        const int kk = (up >> 1) & 3;
        const int h  = up & 1;
        const int ci = kk * 16 + 2 * a + 8 * h;
        __half2 hv = __floats2half2_rn(src[ci], src[ci + 1]);
        v[i] = *reinterpret_cast<uint32_t*>(&hv);
    }
    *reinterpret_cast<uint4*>(g_featsH + (size_t)row * 32 + p0) =
        make_uint4(v[0], v[1], v[2], v[3]);

    if (blockIdx.x < KOFF) {
        const float* Wk = W + blockIdx.x * (CIN * COUT);
        uint32_t* dst = g_WH + blockIdx.x * 2048;
        for (int i = tid; i < 2048; i += 256) {
            // decode: i = lane*64 + kk*16 + j*2 + h ; lane = r*4 + a
            const int lane = i >> 6;
            const int rem  = i & 63;
            const int kk   = rem >> 4;
            const int j    = (rem >> 1) & 7;
            const int h    = rem & 1;
            const int r    = lane >> 2;
            const int a    = lane & 3;
            const int ci   = kk * 16 + 2 * a + 8 * h;
            const int co   = j * 8 + r;
            __half2 hv = __floats2half2_rn(Wk[ci * COUT + co],
                                           Wk[(ci + 1) * COUT + co]);
            dst[i] = *reinterpret_cast<uint32_t*>(&hv);
        }
    }
}

// ---------------------------------------------------------------------------
// Kernel 1: sparse conv. fp16 vector gather -> mma.sync m16n8k16 ->
//           smem stage -> cp.reduce.async.bulk scatter (double buffered).
// Block: 256 threads (8 warps). Warp: 16 pairs/tile, block 128, 4 tiles.
// grid = (M/512, K)
// ---------------------------------------------------------------------------
__global__ void __launch_bounds__(256)
conv_kernel(const int* __restrict__ in_map,
            const int* __restrict__ out_map,
            float*     __restrict__ out)
{
    extern __shared__ char dynsmem[];
    uint32_t* WsP  = reinterpret_cast<uint32_t*>(dynsmem);
    float*    buf0 = reinterpret_cast<float*>(dynsmem + WSP_BYTES);
    float*    buf1 = buf0 + 128 * BUF_STRIDE;

    const int k   = blockIdx.y;
    const int tid = threadIdx.x;

    // Copy per-lane W blocks (already packed) into padded smem.
    {
        const uint32_t* WHk = g_WH + k * 2048;
        for (int i = tid; i < 2048; i += 256)
            WsP[(i >> 6) * WSP_STRIDE + (i & 63)] = WHk[i];
    }
    __syncthreads();

    const int warp = tid >> 5;
    const int lane = tid & 31;
    const int r = lane >> 2;   // 0..7
    const int a = lane & 3;    // 0..3

    const int* im = in_map  + k * MPAIR;
    const int* om = out_map + k * MPAIR;
    const uint32_t* Bl = WsP + lane * WSP_STRIDE;

    #pragma unroll 1
    for (int t = 0; t < 4; t++) {
        const int base = (blockIdx.x * 4 + t) * 128 + warp * 16;
        const int p0 = base + r;
        const int p1 = p0 + 8;

        // Gather: each lane reads its 8 uints (32B) from each of two rows.
        const uint4* r0p = reinterpret_cast<const uint4*>(
            g_featsH + (size_t)im[p0] * 32 + (a << 3));
        const uint4* r1p = reinterpret_cast<const uint4*>(
            g_featsH + (size_t)im[p1] * 32 + (a << 3));
        uint32_t A0[8], A1[8];
        *reinterpret_cast<uint4*>(A0)     = r0p[0];
        *reinterpret_cast<uint4*>(A0 + 4) = r0p[1];
        *reinterpret_cast<uint4*>(A1)     = r1p[0];
        *reinterpret_cast<uint4*>(A1 + 4) = r1p[1];

        float acc[8][4];
        #pragma unroll
        for (int j = 0; j < 8; j++)
            #pragma unroll
            for (int q = 0; q < 4; q++) acc[j][q] = 0.f;

        #pragma unroll
        for (int kk = 0; kk < 4; kk++) {
            uint32_t Bk[16];
            #pragma unroll
            for (int i = 0; i < 4; i++)
                *reinterpret_cast<uint4*>(Bk + 4 * i) =
                    *reinterpret_cast<const uint4*>(Bl + kk * 16 + 4 * i);

            const uint32_t a0 = A0[2 * kk];       // rows r   : cols 2a,2a+1
            const uint32_t a1 = A1[2 * kk];       // rows r+8
            const uint32_t a2 = A0[2 * kk + 1];   // rows r   : cols 2a+8,+9
            const uint32_t a3 = A1[2 * kk + 1];

            #pragma unroll
            for (int j = 0; j < 8; j++) {
                asm volatile(
                    "mma.sync.aligned.m16n8k16.row.col.f32.f16.f16.f32 "
                    "{%0,%1,%2,%3}, {%4,%5,%6,%7}, {%8,%9}, {%0,%1,%2,%3};"
                    : "+f"(acc[j][0]), "+f"(acc[j][1]),
                      "+f"(acc[j][2]), "+f"(acc[j][3])
                    : "r"(a0), "r"(a1), "r"(a2), "r"(a3),
                      "r"(Bk[2 * j]), "r"(Bk[2 * j + 1]));
            }
        }

        // --- Epilogue: stage 16 rows, scatter via TMA bulk reduce-add. ---
        float* wbuf = ((t & 1) ? buf1 : buf0) + warp * 16 * BUF_STRIDE;

        // Double buffer: the group that used THIS buffer (2 tiles ago)
        // must have finished READING its smem staging rows.
        asm volatile("cp.async.bulk.wait_group.read 1;" ::: "memory");
        __syncwarp();

        // mma D layout: lane(r,a) holds D[r, j*8+2a..+1], D[r+8, ...].
        #pragma unroll
        for (int j = 0; j < 8; j++) {
            *reinterpret_cast<float2*>(wbuf + r * BUF_STRIDE + j * 8 + 2 * a)
                = make_float2(acc[j][0], acc[j][1]);
            *reinterpret_cast<float2*>(wbuf + (r + 8) * BUF_STRIDE + j * 8 + 2 * a)
                = make_float2(acc[j][2], acc[j][3]);
        }
        __syncwarp();
        asm volatile("fence.proxy.async.shared::cta;" ::: "memory");

        if (lane < 16) {
            float* dst = out + (size_t)om[base + lane] * COUT;
            uint32_t src = smem_u32(wbuf + lane * BUF_STRIDE);
            asm volatile(
                "cp.reduce.async.bulk.global.shared::cta.bulk_group.add.f32 "
                "[%0], [%1], %2;"
                :: "l"(dst), "r"(src), "r"(256) : "memory");
        }
        asm volatile("cp.async.bulk.commit_group;" ::: "memory");
    }

    // All reduce writes must complete before kernel end.
    asm volatile("cp.async.bulk.wait_group 0;" ::: "memory");
}

// ---------------------------------------------------------------------------
// Kernel 2: per-column sum / sumsq over the conv output
// grid = 2048 blocks x 256 threads, 128 rows per block
// ---------------------------------------------------------------------------
__global__ void stats_kernel(const float* __restrict__ out) {
    __shared__ float ssum[256], ssq[256];
    const int tid = threadIdx.x;
    const int col = tid & 63;
    const int q   = tid >> 6;
    const int rowbase = blockIdx.x * 128;

    float s = 0.f, s2 = 0.f;
    #pragma unroll 8
    for (int i = 0; i < 32; i++) {
        float v = out[(size_t)(rowbase + i * 4 + q) * COUT + col];
        s += v; s2 += v * v;
    }
    ssum[tid] = s; ssq[tid] = s2;
    __syncthreads();
    if (q == 0) {
        s  = ssum[col] + ssum[col + 64] + ssum[col + 128] + ssum[col + 192];
        s2 = ssq[col]  + ssq[col + 64]  + ssq[col + 128]  + ssq[col + 192];
        atomicAdd(&g_sum[col], s);
        atomicAdd(&g_sumsq[col], s2);
    }
}

// ---------------------------------------------------------------------------
// Kernel 3: BN affine + LeakyReLU, in place, float4 vectorized
// ---------------------------------------------------------------------------
__global__ void apply_kernel(float* __restrict__ out,
                             const float* __restrict__ gamma,
                             const float* __restrict__ beta)
{
    __shared__ float sc[COUT], bi[COUT];
    const int tid = threadIdx.x;
    if (tid < COUT) {
        const float inv_n = 1.f / (float)NOUT;
        float mean = g_sum[tid] * inv_n;
        float var  = g_sumsq[tid] * inv_n - mean * mean;
        float s = gamma[tid] * rsqrtf(var + EPS);
        sc[tid] = s;
        bi[tid] = beta[tid] - mean * s;
    }
    __syncthreads();

    const int idx = blockIdx.x * blockDim.x + tid;   // over 4,194,304 float4
    float4* o4 = reinterpret_cast<float4*>(out);
    float4 v = o4[idx];
    const int c = (idx & 15) * 4;
    float y0 = v.x * sc[c + 0] + bi[c + 0];
    float y1 = v.y * sc[c + 1] + bi[c + 1];
    float y2 = v.z * sc[c + 2] + bi[c + 2];
    float y3 = v.w * sc[c + 3] + bi[c + 3];
    v.x = (y0 >= 0.f) ? y0 : SLOPE * y0;
    v.y = (y1 >= 0.f) ? y1 : SLOPE * y1;
    v.z = (y2 >= 0.f) ? y2 : SLOPE * y2;
    v.w = (y3 >= 0.f) ? y3 : SLOPE * y3;
    o4[idx] = v;
}

// ---------------------------------------------------------------------------
// Launch
// inputs (metadata order): feats f32[N_IN*64], W f32[27*64*64], gamma f32[64],
//   beta f32[64], in_map i32[27*M], out_map i32[27*M], num_out i32[1]
// ---------------------------------------------------------------------------
extern "C" void kernel_launch(void* const* d_in, const int* in_sizes, int n_in,
                              void* d_out, int out_size)
{
    const float* feats   = (const float*)d_in[0];
    const float* W       = (const float*)d_in[1];
    const float* gamma   = (const float*)d_in[2];
    const float* beta    = (const float*)d_in[3];
    const int*   in_map  = (const int*)d_in[4];
    const int*   out_map = (const int*)d_in[5];
    float*       out     = (float*)d_out;

    const int n_f4 = (NOUT * COUT) / 4;          // 4,194,304

    zero_kernel<<<n_f4 / 256, 256>>>(reinterpret_cast<float4*>(out));
    precvt_kernel<<<8192, 256>>>(feats, W);

    cudaFuncSetAttribute(conv_kernel,
                         cudaFuncAttributeMaxDynamicSharedMemorySize,
                         SMEM_BYTES);
    dim3 grid(MPAIR / 512, KOFF);                // 256 x 27
    conv_kernel<<<grid, 256, SMEM_BYTES>>>(in_map, out_map, out);

    stats_kernel<<<2048, 256>>>(out);

    apply_kernel<<<n_f4 / 256, 256>>>(out, gamma, beta);
}

// round 6
// speedup vs baseline: 1.7426x; 1.1818x over previous
#include <cuda_runtime.h>
#include <cuda_fp16.h>
#include <cstdint>

// Problem constants (fixed by the reference)
#define CIN   64
#define COUT  64
#define KOFF  27
#define MPAIR 131072
#define NOUT  262144
#define NIN   262144
#define EPS   1e-5f
#define SLOPE 0.01f

// smem layout for conv kernel (dynamic):
//   [0, 8704)   : WsP — per-lane fp16x2 W blocks, 32 lanes x 68 uints
//   [8704, ..)  : buf0, buf1 — 2 x (128 staging rows x 68 floats)
#define WSP_STRIDE 68                    // uints per lane (64 + 4 pad)
#define WSP_BYTES  (32 * WSP_STRIDE * 4) // 8704
#define BUF_STRIDE 68                    // floats; 272B row stride, 16B mult
#define BUF_BYTES  (128 * BUF_STRIDE * 4)
#define SMEM_BYTES (WSP_BYTES + 2 * BUF_BYTES)

// Pre-converted fp16 operands (device scratch; no runtime allocation)
// feats row layout (32 uints = 64 fp16): uint index p = a*8 + kk*2 + h
// holds half2( feats[ci], feats[ci+1] ), ci = kk*16 + 2a + 8h.
__device__ uint32_t g_featsH[NIN * 32];          // 33.5 MB
// W layout per k: 32 lanes x 64 uints; lane (r,a), uint kk*16 + j*2 + h
// holds half2( W[ci][co], W[ci+1][co] ), ci = kk*16+2a+8h, co = j*8+r.
__device__ uint32_t g_WH[KOFF * 2048];           // 216 KB

// BN statistics scratch
__device__ float g_sum[COUT];
__device__ float g_sumsq[COUT];

__device__ __forceinline__ uint32_t smem_u32(const void* p) {
    uint32_t a;
    asm("{ .reg .u64 t; cvta.to.shared.u64 t, %1; cvt.u32.u64 %0, t; }"
        : "=r"(a) : "l"(p));
    return a;
}

// ---------------------------------------------------------------------------
// Kernel 0: fused zero(out) + pre-convert feats/W to fp16 fragment layouts.
// grid = 8192 x 256. Each thread: zeros 2 float4s of out, produces 4 uints
// of g_featsH. Blocks 0..26 also pack W[k]. Block 0 zeroes BN scratch.
// ---------------------------------------------------------------------------
__global__ void __launch_bounds__(256)
precvt_kernel(const float* __restrict__ feats, const float* __restrict__ W,
              float4* __restrict__ out4)
{
    const int tid = threadIdx.x;
    const int t4  = blockIdx.x * 256 + tid;        // 0 .. 2,097,151

    // zero the 67 MB accumulator (2 float4s per thread)
    const float4 z = make_float4(0.f, 0.f, 0.f, 0.f);
    out4[2 * (size_t)t4]     = z;
    out4[2 * (size_t)t4 + 1] = z;
    if (blockIdx.x == 0 && tid < COUT) {
        g_sum[tid]   = 0.f;
        g_sumsq[tid] = 0.f;
    }

    const int row = t4 >> 3;
    const int p0  = (t4 & 7) << 2;                 // first of 4 uint slots

    const float* src = feats + (size_t)row * CIN;
    uint32_t v[4];
    #pragma unroll
    for (int i = 0; i < 4; i++) {
        const int up = p0 + i;
        const int a  = up >> 3;
        const int kk = (up >> 1) & 3;
        const int h  = up & 1;
        const int ci = kk * 16 + 2 * a + 8 * h;
        __half2 hv = __floats2half2_rn(src[ci], src[ci + 1]);
        v[i] = *reinterpret_cast<uint32_t*>(&hv);
    }
    *reinterpret_cast<uint4*>(g_featsH + (size_t)row * 32 + p0) =
        make_uint4(v[0], v[1], v[2], v[3]);

    if (blockIdx.x < KOFF) {
        const float* Wk = W + blockIdx.x * (CIN * COUT);
        uint32_t* dst = g_WH + blockIdx.x * 2048;
        for (int i = tid; i < 2048; i += 256) {
            // decode: i = lane*64 + kk*16 + j*2 + h ; lane = r*4 + a
            const int lane = i >> 6;
            const int rem  = i & 63;
            const int kk   = rem >> 4;
            const int j    = (rem >> 1) & 7;
            const int h    = rem & 1;
            const int r    = lane >> 2;
            const int a    = lane & 3;
            const int ci   = kk * 16 + 2 * a + 8 * h;
            const int co   = j * 8 + r;
            __half2 hv = __floats2half2_rn(Wk[ci * COUT + co],
                                           Wk[(ci + 1) * COUT + co]);
            dst[i] = *reinterpret_cast<uint32_t*>(&hv);
        }
    }
}

// ---------------------------------------------------------------------------
// Kernel 1: sparse conv. Software-pipelined fp16 gather -> mma m16n8k16 ->
//           smem stage -> cp.reduce.async.bulk scatter (double buffered).
// Block: 256 threads (8 warps). Warp: 16 pairs/tile, block 128, 4 tiles
// (fully unrolled, gather for t+1 issued before MMA of t).
// grid = (M/512, K)
// ---------------------------------------------------------------------------
__global__ void __launch_bounds__(256, 2)
conv_kernel(const int* __restrict__ in_map,
            const int* __restrict__ out_map,
            float*     __restrict__ out)
{
    extern __shared__ char dynsmem[];
    uint32_t* WsP  = reinterpret_cast<uint32_t*>(dynsmem);
    float*    buf0 = reinterpret_cast<float*>(dynsmem + WSP_BYTES);
    float*    buf1 = buf0 + 128 * BUF_STRIDE;

    const int k   = blockIdx.y;
    const int tid = threadIdx.x;

    // Copy per-lane W blocks (already packed) into padded smem.
    {
        const uint32_t* WHk = g_WH + k * 2048;
        for (int i = tid; i < 2048; i += 256)
            WsP[(i >> 6) * WSP_STRIDE + (i & 63)] = WHk[i];
    }

    const int warp = tid >> 5;
    const int lane = tid & 31;
    const int r = lane >> 2;   // 0..7
    const int a = lane & 3;    // 0..3

    const int* im = in_map  + k * MPAIR;
    const int* om = out_map + k * MPAIR;
    const uint32_t* Bl = WsP + lane * WSP_STRIDE;

    const int base0 = blockIdx.x * 512 + warp * 16;

    // ---- Prologue: gather tile 0 ----
    uint32_t A0[16];
    int orow = (lane < 16) ? om[base0 + lane] : 0;
    {
        const uint4* r0p = reinterpret_cast<const uint4*>(
            g_featsH + (size_t)im[base0 + r] * 32 + (a << 3));
        const uint4* r1p = reinterpret_cast<const uint4*>(
            g_featsH + (size_t)im[base0 + r + 8] * 32 + (a << 3));
        *reinterpret_cast<uint4*>(A0)      = r0p[0];
        *reinterpret_cast<uint4*>(A0 + 4)  = r0p[1];
        *reinterpret_cast<uint4*>(A0 + 8)  = r1p[0];
        *reinterpret_cast<uint4*>(A0 + 12) = r1p[1];
    }
    __syncthreads();   // WsP ready (also covers prologue)

    #pragma unroll
    for (int t = 0; t < 4; t++) {
        // ---- Prefetch tile t+1 (indices + A rows + out row) ----
        uint32_t An[16];
        int orow_n = 0;
        if (t < 3) {
            const int basen = base0 + (t + 1) * 128;
            if (lane < 16) orow_n = om[basen + lane];
            const uint4* r0p = reinterpret_cast<const uint4*>(
                g_featsH + (size_t)im[basen + r] * 32 + (a << 3));
            const uint4* r1p = reinterpret_cast<const uint4*>(
                g_featsH + (size_t)im[basen + r + 8] * 32 + (a << 3));
            *reinterpret_cast<uint4*>(An)      = r0p[0];
            *reinterpret_cast<uint4*>(An + 4)  = r0p[1];
            *reinterpret_cast<uint4*>(An + 8)  = r1p[0];
            *reinterpret_cast<uint4*>(An + 12) = r1p[1];
        }

        // ---- MMA on tile t ----
        float acc[8][4];
        #pragma unroll
        for (int j = 0; j < 8; j++)
            #pragma unroll
            for (int q = 0; q < 4; q++) acc[j][q] = 0.f;

        #pragma unroll
        for (int kk = 0; kk < 4; kk++) {
            uint32_t Bk[16];
            #pragma unroll
            for (int i = 0; i < 4; i++)
                *reinterpret_cast<uint4*>(Bk + 4 * i) =
                    *reinterpret_cast<const uint4*>(Bl + kk * 16 + 4 * i);

            const uint32_t a0 = A0[2 * kk];       // rows r   : cols 2a,2a+1
            const uint32_t a1 = A0[8 + 2 * kk];   // rows r+8
            const uint32_t a2 = A0[2 * kk + 1];   // rows r   : cols 2a+8,+9
            const uint32_t a3 = A0[8 + 2 * kk + 1];

            #pragma unroll
            for (int j = 0; j < 8; j++) {
                asm volatile(
                    "mma.sync.aligned.m16n8k16.row.col.f32.f16.f16.f32 "
                    "{%0,%1,%2,%3}, {%4,%5,%6,%7}, {%8,%9}, {%0,%1,%2,%3};"
                    : "+f"(acc[j][0]), "+f"(acc[j][1]),
                      "+f"(acc[j][2]), "+f"(acc[j][3])
                    : "r"(a0), "r"(a1), "r"(a2), "r"(a3),
                      "r"(Bk[2 * j]), "r"(Bk[2 * j + 1]));
            }
        }

        // ---- Epilogue: stage 16 rows, scatter via TMA bulk reduce-add ----
        float* wbuf = ((t & 1) ? buf1 : buf0) + warp * 16 * BUF_STRIDE;

        // Double buffer: the group that used THIS buffer (2 tiles ago)
        // must have finished READING its smem staging rows.
        asm volatile("cp.async.bulk.wait_group.read 1;" ::: "memory");
        __syncwarp();

        // mma D layout: lane(r,a) holds D[r, j*8+2a..+1], D[r+8, ...].
        #pragma unroll
        for (int j = 0; j < 8; j++) {
            *reinterpret_cast<float2*>(wbuf + r * BUF_STRIDE + j * 8 + 2 * a)
                = make_float2(acc[j][0], acc[j][1]);
            *reinterpret_cast<float2*>(wbuf + (r + 8) * BUF_STRIDE + j * 8 + 2 * a)
                = make_float2(acc[j][2], acc[j][3]);
        }
        __syncwarp();
        asm volatile("fence.proxy.async.shared::cta;" ::: "memory");

        if (lane < 16) {
            float* dst = out + (size_t)orow * COUT;
            uint32_t src = smem_u32(wbuf + lane * BUF_STRIDE);
            asm volatile(
                "cp.reduce.async.bulk.global.shared::cta.bulk_group.add.f32 "
                "[%0], [%1], %2;"
                :: "l"(dst), "r"(src), "r"(256) : "memory");
        }
        asm volatile("cp.async.bulk.commit_group;" ::: "memory");

        // rotate pipeline registers
        orow = orow_n;
        #pragma unroll
        for (int i = 0; i < 16; i++) A0[i] = An[i];
    }

    // All reduce writes must complete before kernel end.
    asm volatile("cp.async.bulk.wait_group 0;" ::: "memory");
}

// ---------------------------------------------------------------------------
// Kernel 2: per-column sum / sumsq, float4 loads.
// grid = 1024 blocks x 256 threads; 256 rows per block.
// thread: c4 = tid&15 (float4 within row), q = tid>>4 (row group of 16)
// ---------------------------------------------------------------------------
__global__ void stats_kernel(const float4* __restrict__ out4) {
    __shared__ float4 ssum[256], ssq[256];
    const int tid = threadIdx.x;
    const int c4  = tid & 15;
    const int q   = tid >> 4;
    const int rowbase = blockIdx.x * 256;

    float4 s  = make_float4(0.f, 0.f, 0.f, 0.f);
    float4 s2 = make_float4(0.f, 0.f, 0.f, 0.f);
    #pragma unroll 16
    for (int i = 0; i < 16; i++) {
        const float4 v = out4[(size_t)(rowbase + i * 16 + q) * 16 + c4];
        s.x += v.x; s.y += v.y; s.z += v.z; s.w += v.w;
        s2.x += v.x * v.x; s2.y += v.y * v.y;
        s2.z += v.z * v.z; s2.w += v.w * v.w;
    }
    ssum[tid] = s; ssq[tid] = s2;
    __syncthreads();
    if (q == 0) {
        float4 ts  = make_float4(0.f, 0.f, 0.f, 0.f);
        float4 ts2 = make_float4(0.f, 0.f, 0.f, 0.f);
        #pragma unroll
        for (int g = 0; g < 16; g++) {
            const float4 u = ssum[g * 16 + c4];
            const float4 u2 = ssq[g * 16 + c4];
            ts.x += u.x; ts.y += u.y; ts.z += u.z; ts.w += u.w;
            ts2.x += u2.x; ts2.y += u2.y; ts2.z += u2.z; ts2.w += u2.w;
        }
        atomicAdd(&g_sum[c4 * 4 + 0], ts.x);
        atomicAdd(&g_sum[c4 * 4 + 1], ts.y);
        atomicAdd(&g_sum[c4 * 4 + 2], ts.z);
        atomicAdd(&g_sum[c4 * 4 + 3], ts.w);
        atomicAdd(&g_sumsq[c4 * 4 + 0], ts2.x);
        atomicAdd(&g_sumsq[c4 * 4 + 1], ts2.y);
        atomicAdd(&g_sumsq[c4 * 4 + 2], ts2.z);
        atomicAdd(&g_sumsq[c4 * 4 + 3], ts2.w);
    }
}

// ---------------------------------------------------------------------------
// Kernel 3: BN affine + LeakyReLU, in place, float4 vectorized
// ---------------------------------------------------------------------------
__global__ void apply_kernel(float* __restrict__ out,
                             const float* __restrict__ gamma,
                             const float* __restrict__ beta)
{
    __shared__ float sc[COUT], bi[COUT];
    const int tid = threadIdx.x;
    if (tid < COUT) {
        const float inv_n = 1.f / (float)NOUT;
        float mean = g_sum[tid] * inv_n;
        float var  = g_sumsq[tid] * inv_n - mean * mean;
        float s = gamma[tid] * rsqrtf(var + EPS);
        sc[tid] = s;
        bi[tid] = beta[tid] - mean * s;
    }
    __syncthreads();

    const int idx = blockIdx.x * blockDim.x + tid;   // over 4,194,304 float4
    float4* o4 = reinterpret_cast<float4*>(out);
    float4 v = o4[idx];
    const int c = (idx & 15) * 4;
    float y0 = v.x * sc[c + 0] + bi[c + 0];
    float y1 = v.y * sc[c + 1] + bi[c + 1];
    float y2 = v.z * sc[c + 2] + bi[c + 2];
    float y3 = v.w * sc[c + 3] + bi[c + 3];
    v.x = (y0 >= 0.f) ? y0 : SLOPE * y0;
    v.y = (y1 >= 0.f) ? y1 : SLOPE * y1;
    v.z = (y2 >= 0.f) ? y2 : SLOPE * y2;
    v.w = (y3 >= 0.f) ? y3 : SLOPE * y3;
    o4[idx] = v;
}

// ---------------------------------------------------------------------------
// Launch
// inputs (metadata order): feats f32[N_IN*64], W f32[27*64*64], gamma f32[64],
//   beta f32[64], in_map i32[27*M], out_map i32[27*M], num_out i32[1]
// ---------------------------------------------------------------------------
extern "C" void kernel_launch(void* const* d_in, const int* in_sizes, int n_in,
                              void* d_out, int out_size)
{
    const float* feats   = (const float*)d_in[0];
    const float* W       = (const float*)d_in[1];
    const float* gamma   = (const float*)d_in[2];
    const float* beta    = (const float*)d_in[3];
    const int*   in_map  = (const int*)d_in[4];
    const int*   out_map = (const int*)d_in[5];
    float*       out     = (float*)d_out;

    const int n_f4 = (NOUT * COUT) / 4;          // 4,194,304

    precvt_kernel<<<8192, 256>>>(feats, W, reinterpret_cast<float4*>(out));

    cudaFuncSetAttribute(conv_kernel,
                         cudaFuncAttributeMaxDynamicSharedMemorySize,
                         SMEM_BYTES);
    dim3 grid(MPAIR / 512, KOFF);                // 256 x 27
    conv_kernel<<<grid, 256, SMEM_BYTES>>>(in_map, out_map, out);

    stats_kernel<<<1024, 256>>>(reinterpret_cast<const float4*>(out));

    apply_kernel<<<n_f4 / 256, 256>>>(out, gamma, beta);
}